// round 12
// baseline (speedup 1.0000x reference)
#include <cuda_runtime.h>
#include <cuda_bf16.h>
#include <cstdio>

#define N_NODES 50000
#define N_EDGES 800000
#define DIM 64
#define N_GRAPHS 256
#define N_LAYERS 3
#define D3 (DIM * N_LAYERS)   // 192
#define NV (N_NODES * DIM)    // 3,200,000

#define ZT_STRIDE 132         // padded row stride for transposed tiles
#define N_PAD 53248           // 1024 * 52, padded node count for scan

// ---------------- scratch (device globals; no allocation allowed) ----------
__device__ __align__(16) float g_z [NV];      // aggregated input (h + sum nbrs)
__device__ __align__(16) float g_z2[NV];      // post-MLP, pre-BN
__device__ __align__(16) float g_h [NV];      // post-BN (next layer input)
__device__ float g_stats[N_LAYERS * 2 * DIM]; // per-layer [sum | sumsq]
__device__ float g_pooled[N_GRAPHS * D3];

__device__ __align__(16) int g_cnt   [N_PAD]; // per-dst degree (histogram)
__device__ int g_rowptr[N_PAD];
__device__ int g_cursor[N_PAD];
__device__ int g_srcsorted[N_EDGES];

// ---------------------------------------------------------------------------
__global__ void k_zero_all() {
    int i = blockIdx.x * blockDim.x + threadIdx.x;
    if (i < N_PAD) g_cnt[i] = 0;
    else if (i < N_PAD + N_LAYERS * 2 * DIM) g_stats[i - N_PAD] = 0.f;
    else if (i < N_PAD + N_LAYERS * 2 * DIM + N_GRAPHS * D3)
        g_pooled[i - N_PAD - N_LAYERS * 2 * DIM] = 0.f;
}

__global__ void k_hist(const int* __restrict__ dst) {
    int e = blockIdx.x * blockDim.x + threadIdx.x;
    if (e < N_EDGES) atomicAdd(&g_cnt[dst[e]], 1);
}

// single-block exclusive scan of g_cnt -> g_rowptr/g_cursor (1024 thr x 52)
__global__ void __launch_bounds__(1024) k_scan() {
    const int t = threadIdx.x;
    const int lane = t & 31, wid = t >> 5;
    const int base = t * 52;
    int s = 0;
#pragma unroll
    for (int i = 0; i < 13; i++) {
        int4 c = *(const int4*)&g_cnt[base + i * 4];
        s += c.x + c.y + c.z + c.w;
    }
    int v = s;
#pragma unroll
    for (int o = 1; o < 32; o <<= 1) {
        int n = __shfl_up_sync(0xffffffffu, v, o);
        if (lane >= o) v += n;
    }
    __shared__ int wsum[32];
    if (lane == 31) wsum[wid] = v;
    __syncthreads();
    if (wid == 0) {
        int w = wsum[lane];
#pragma unroll
        for (int o = 1; o < 32; o <<= 1) {
            int n = __shfl_up_sync(0xffffffffu, w, o);
            if (lane >= o) w += n;
        }
        wsum[lane] = w;
    }
    __syncthreads();
    int ex = v - s + (wid > 0 ? wsum[wid - 1] : 0);
    int acc = ex;
#pragma unroll
    for (int i = 0; i < 13; i++) {
        int4 c = *(const int4*)&g_cnt[base + i * 4];
        int p0 = acc, p1 = p0 + c.x, p2 = p1 + c.y, p3 = p2 + c.z;
        *(int4*)&g_rowptr[base + i * 4] = make_int4(p0, p1, p2, p3);
        *(int4*)&g_cursor[base + i * 4] = make_int4(p0, p1, p2, p3);
        acc = p3 + c.w;
    }
}

__global__ void k_permute(const int* __restrict__ src,
                          const int* __restrict__ dst) {
    int e = blockIdx.x * blockDim.x + threadIdx.x;
    if (e < N_EDGES) {
        int pos = atomicAdd(&g_cursor[dst[e]], 1);
        g_srcsorted[pos] = src[e];
    }
}

// ---------------------------------------------------------------------------
// CSR gather, high occupancy: thread = (node, float4 chunk).
// g_z[node] = h[node] + sum_{j->node} h[j]
__global__ void __launch_bounds__(256) k_gather(
        const float* __restrict__ xin, int use_x) {
    int gid = blockIdx.x * blockDim.x + threadIdx.x;
    int node = gid >> 4;
    int chunk = gid & 15;
    if (node >= N_NODES) return;
    const float4* __restrict__ hin4 =
        use_x ? (const float4*)xin : (const float4*)g_h;

    float4 a = hin4[(size_t)node * 16 + chunk];
    int beg = g_rowptr[node];
    int deg = g_cnt[node];
    int j = 0;
    for (; j + 4 <= deg; j += 4) {
        int s0 = g_srcsorted[beg + j + 0];
        int s1 = g_srcsorted[beg + j + 1];
        int s2 = g_srcsorted[beg + j + 2];
        int s3 = g_srcsorted[beg + j + 3];
        float4 v0 = hin4[(size_t)s0 * 16 + chunk];
        float4 v1 = hin4[(size_t)s1 * 16 + chunk];
        float4 v2 = hin4[(size_t)s2 * 16 + chunk];
        float4 v3 = hin4[(size_t)s3 * 16 + chunk];
        a.x += (v0.x + v1.x) + (v2.x + v3.x);
        a.y += (v0.y + v1.y) + (v2.y + v3.y);
        a.z += (v0.z + v1.z) + (v2.z + v3.z);
        a.w += (v0.w + v1.w) + (v2.w + v3.w);
    }
    for (; j < deg; j++) {
        int s0 = g_srcsorted[beg + j];
        float4 v0 = hin4[(size_t)s0 * 16 + chunk];
        a.x += v0.x; a.y += v0.y; a.z += v0.z; a.w += v0.w;
    }
    ((float4*)g_z)[(size_t)node * 16 + chunk] = a;
}

// ---------------------------------------------------------------------------
// Tiled MLP: z2 = relu( relu(z @ W1 + B1) @ W2 + B2 ) + fused BN stats.
// Block tile: 128 nodes x 64 features, 256 threads, thread tile 8x4.
__global__ void __launch_bounds__(256, 2) k_mlp(
        int layer,
        const float* __restrict__ W1, const float* __restrict__ B1,
        const float* __restrict__ W2, const float* __restrict__ B2) {
    extern __shared__ float smem[];
    float* sZT = smem;                        // [64][ZT_STRIDE] transposed z
    float* sW  = sZT + 64 * ZT_STRIDE;        // [64][64]
    float* sHT = sW + 64 * 64;                // [64][ZT_STRIDE] transposed hidden

    const int t  = threadIdx.x;
    const int tm = t & 15;
    const int tn = t >> 4;
    const int blockNode = blockIdx.x * 128;
    float* stats = g_stats + layer * 2 * DIM;

    for (int i = t; i < DIM * DIM; i += 256) sW[i] = W1[i];
    {
        int nLoc = t & 15;
        int f4   = t >> 4;
#pragma unroll
        for (int s = 0; s < 8; s++) {
            int m = s * 16 + nLoc;
            int node = blockNode + m;
            float4 v = make_float4(0.f, 0.f, 0.f, 0.f);
            if (node < N_NODES)
                v = ((const float4*)g_z)[(size_t)node * 16 + f4];
            sZT[(4 * f4 + 0) * ZT_STRIDE + m] = v.x;
            sZT[(4 * f4 + 1) * ZT_STRIDE + m] = v.y;
            sZT[(4 * f4 + 2) * ZT_STRIDE + m] = v.z;
            sZT[(4 * f4 + 3) * ZT_STRIDE + m] = v.w;
        }
    }
    __syncthreads();

    float acc[8][4];
    {
        float b0 = B1[4 * tn + 0], b1 = B1[4 * tn + 1];
        float b2 = B1[4 * tn + 2], b3 = B1[4 * tn + 3];
#pragma unroll
        for (int i = 0; i < 8; i++) {
            acc[i][0] = b0; acc[i][1] = b1; acc[i][2] = b2; acc[i][3] = b3;
        }
    }
#pragma unroll 4
    for (int k = 0; k < DIM; k++) {
        float4 a0 = *(const float4*)&sZT[k * ZT_STRIDE + 8 * tm];
        float4 a1 = *(const float4*)&sZT[k * ZT_STRIDE + 8 * tm + 4];
        float4 b  = *(const float4*)&sW[k * DIM + 4 * tn];
        float av[8] = {a0.x, a0.y, a0.z, a0.w, a1.x, a1.y, a1.z, a1.w};
#pragma unroll
        for (int i = 0; i < 8; i++) {
            acc[i][0] += av[i] * b.x;
            acc[i][1] += av[i] * b.y;
            acc[i][2] += av[i] * b.z;
            acc[i][3] += av[i] * b.w;
        }
    }
#pragma unroll
    for (int i = 0; i < 8; i++) {
        int m = 8 * tm + i;
#pragma unroll
        for (int j = 0; j < 4; j++)
            sHT[(4 * tn + j) * ZT_STRIDE + m] = fmaxf(acc[i][j], 0.f);
    }
    __syncthreads();
    for (int i = t; i < DIM * DIM; i += 256) sW[i] = W2[i];
    __syncthreads();

    {
        float b0 = B2[4 * tn + 0], b1 = B2[4 * tn + 1];
        float b2 = B2[4 * tn + 2], b3 = B2[4 * tn + 3];
#pragma unroll
        for (int i = 0; i < 8; i++) {
            acc[i][0] = b0; acc[i][1] = b1; acc[i][2] = b2; acc[i][3] = b3;
        }
    }
#pragma unroll 4
    for (int k = 0; k < DIM; k++) {
        float4 a0 = *(const float4*)&sHT[k * ZT_STRIDE + 8 * tm];
        float4 a1 = *(const float4*)&sHT[k * ZT_STRIDE + 8 * tm + 4];
        float4 b  = *(const float4*)&sW[k * DIM + 4 * tn];
        float av[8] = {a0.x, a0.y, a0.z, a0.w, a1.x, a1.y, a1.z, a1.w};
#pragma unroll
        for (int i = 0; i < 8; i++) {
            acc[i][0] += av[i] * b.x;
            acc[i][1] += av[i] * b.y;
            acc[i][2] += av[i] * b.z;
            acc[i][3] += av[i] * b.w;
        }
    }

    float psum[4] = {0.f, 0.f, 0.f, 0.f};
    float psq [4] = {0.f, 0.f, 0.f, 0.f};
#pragma unroll
    for (int i = 0; i < 8; i++) {
        int node = blockNode + 8 * tm + i;
        float v0 = fmaxf(acc[i][0], 0.f);
        float v1 = fmaxf(acc[i][1], 0.f);
        float v2 = fmaxf(acc[i][2], 0.f);
        float v3 = fmaxf(acc[i][3], 0.f);
        if (node < N_NODES) {
            *(float4*)(g_z2 + (size_t)node * DIM + 4 * tn) =
                make_float4(v0, v1, v2, v3);
            psum[0] += v0; psum[1] += v1; psum[2] += v2; psum[3] += v3;
            psq[0] += v0 * v0; psq[1] += v1 * v1;
            psq[2] += v2 * v2; psq[3] += v3 * v3;
        }
    }
#pragma unroll
    for (int ofs = 1; ofs <= 8; ofs <<= 1) {
#pragma unroll
        for (int j = 0; j < 4; j++) {
            psum[j] += __shfl_xor_sync(0xffffffffu, psum[j], ofs);
            psq [j] += __shfl_xor_sync(0xffffffffu, psq [j], ofs);
        }
    }
    if (tm == 0) {
#pragma unroll
        for (int j = 0; j < 4; j++) {
            atomicAdd(&stats[4 * tn + j], psum[j]);
            atomicAdd(&stats[DIM + 4 * tn + j], psq[j]);
        }
    }
}

// ---------------------------------------------------------------------------
// BN apply + next-layer input + pooled accumulation (run-length atomics).
__global__ void __launch_bounds__(256) k_bn(
        const float* __restrict__ gamma,
        const float* __restrict__ beta,
        const int* __restrict__ batch,
        int layer, int last) {
    int t = blockIdx.x * blockDim.x + threadIdx.x;
    int d = t & 63;
    int nodeBase = (t >> 6) * 8;
    if (nodeBase >= N_NODES) return;
    const float* stats = g_stats + layer * 2 * DIM;
    int layerOff = layer * DIM;

    const float invN = 1.f / N_NODES;
    float mean = stats[d] * invN;
    float var  = fmaxf(stats[DIM + d] * invN - mean * mean, 0.f);
    float scale = rsqrtf(var + 1e-5f) * gamma[d];
    float shift = beta[d] - mean * scale;

    int curG = batch[nodeBase];
    float poolAcc = 0.f;
#pragma unroll
    for (int i = 0; i < 8; i++) {
        int node = nodeBase + i;
        if (node >= N_NODES) break;
        size_t idx = (size_t)node * DIM + d;
        float v = g_z2[idx] * scale + shift;
        if (!last) g_h[idx] = v;
        int g = batch[node];
        if (g != curG) {
            atomicAdd(&g_pooled[curG * D3 + layerOff + d], poolAcc);
            poolAcc = 0.f;
            curG = g;
        }
        poolAcc += v;
    }
    atomicAdd(&g_pooled[curG * D3 + layerOff + d], poolAcc);
}

// out = relu(pooled @ PW1 + PB1) @ PW2 + PB2,  one graph per block
__global__ void __launch_bounds__(D3) k_final(
        const float* __restrict__ PW1, const float* __restrict__ PB1,
        const float* __restrict__ PW2, const float* __restrict__ PB2,
        float* __restrict__ out) {
    int g = blockIdx.x;
    int t = threadIdx.x;
    __shared__ float row[D3];
    __shared__ float hid[D3];
    row[t] = g_pooled[g * D3 + t];
    __syncthreads();
    float acc = PB1[t];
#pragma unroll 8
    for (int k = 0; k < D3; k++) acc += row[k] * PW1[k * D3 + t];
    hid[t] = fmaxf(acc, 0.f);
    __syncthreads();
    float a2 = PB2[t];
#pragma unroll 8
    for (int k = 0; k < D3; k++) a2 += hid[k] * PW2[k * D3 + t];
    out[g * D3 + t] = a2;
}

// ---------------------------------------------------------------------------
extern "C" void kernel_launch(void* const* d_in, const int* in_sizes, int n_in,
                              void* d_out, int out_size) {
    const float* x     = (const float*)d_in[0];
    const int*   ei    = (const int*)d_in[1];     // [2, N_EDGES] int32
    const int*   batch = (const int*)d_in[2];     // [N_NODES]    int32
    const float* W1 = (const float*)d_in[3];   // [3,64,64]
    const float* B1 = (const float*)d_in[4];
    const float* W2 = (const float*)d_in[5];
    const float* B2 = (const float*)d_in[6];
    const float* gamma = (const float*)d_in[7];
    const float* beta  = (const float*)d_in[8];
    const float* PW1 = (const float*)d_in[9];
    const float* PB1 = (const float*)d_in[10];
    const float* PW2 = (const float*)d_in[11];
    const float* PB2 = (const float*)d_in[12];
    float* out = (float*)d_out;

    const int* src = ei;
    const int* dst = ei + N_EDGES;

    const int mlpSmem = (64 * ZT_STRIDE + 64 * 64 + 64 * ZT_STRIDE) * 4;
    static int attrDone = 0;
    if (!attrDone) {
        cudaFuncSetAttribute(k_mlp, cudaFuncAttributeMaxDynamicSharedMemorySize,
                             mlpSmem);
        attrDone = 1;
    }

    const int zeroTot = N_PAD + N_LAYERS * 2 * DIM + N_GRAPHS * D3;
    k_zero_all<<<(zeroTot + 255) / 256, 256>>>();
    k_hist<<<(N_EDGES + 255) / 256, 256>>>(dst);
    k_scan<<<1, 1024>>>();
    k_permute<<<(N_EDGES + 255) / 256, 256>>>(src, dst);

    const int gatherThreads = N_NODES * 16;
    const int bnThreads = 64 * ((N_NODES + 7) / 8);
    const int bnBlocks  = (bnThreads + 255) / 256;

    for (int l = 0; l < N_LAYERS; l++) {
        k_gather<<<(gatherThreads + 255) / 256, 256>>>(x, l == 0 ? 1 : 0);
        k_mlp<<<(N_NODES + 127) / 128, 256, mlpSmem>>>(
            l,
            W1 + l * DIM * DIM, B1 + l * DIM,
            W2 + l * DIM * DIM, B2 + l * DIM);
        k_bn<<<bnBlocks, 256>>>(gamma + l * DIM, beta + l * DIM,
                                batch, l, l == N_LAYERS - 1);
    }
    k_final<<<N_GRAPHS, D3>>>(PW1, PB1, PW2, PB2, out);
}

// round 14
// speedup vs baseline: 1.0463x; 1.0463x over previous
#include <cuda_runtime.h>
#include <cuda_bf16.h>
#include <cstdio>

#define N_NODES 50000
#define N_EDGES 800000
#define DIM 64
#define N_GRAPHS 256
#define N_LAYERS 3
#define D3 (DIM * N_LAYERS)   // 192
#define NV (N_NODES * DIM)    // 3,200,000

#define ZT_STRIDE 132         // padded row stride for transposed tiles
#define N_PAD 53248           // 13 * 4096, padded node count for scan

// ---------------- scratch (device globals; no allocation allowed) ----------
__device__ __align__(16) float g_z [NV];      // aggregated input (h + sum nbrs)
__device__ __align__(16) float g_z2[NV];      // post-MLP, pre-BN
__device__ __align__(16) float g_h [NV];      // post-BN (next layer input)
__device__ float g_stats[N_LAYERS * 2 * DIM]; // per-layer [sum | sumsq]
__device__ float g_pooled[N_GRAPHS * D3];

__device__ __align__(16) int g_cnt   [N_PAD]; // per-dst degree (histogram)
__device__ __align__(16) int g_part  [N_PAD]; // scan partials
__device__ int g_bsum[16];
__device__ int g_boff[16];
__device__ int g_rowptr[N_PAD];
__device__ int g_cursor[N_PAD];
__device__ int g_srcsorted[N_EDGES];

// ---------------------------------------------------------------------------
__global__ void k_zero_all() {
    int i = blockIdx.x * blockDim.x + threadIdx.x;
    if (i < N_PAD) g_cnt[i] = 0;
    else if (i < N_PAD + N_LAYERS * 2 * DIM) g_stats[i - N_PAD] = 0.f;
    else if (i < N_PAD + N_LAYERS * 2 * DIM + N_GRAPHS * D3)
        g_pooled[i - N_PAD - N_LAYERS * 2 * DIM] = 0.f;
}

// 4 edges per thread: 4 independent REDs in flight
__global__ void k_hist(const int* __restrict__ dst) {
    int q = blockIdx.x * blockDim.x + threadIdx.x;
    if (q >= N_EDGES / 4) return;
    int4 d = ((const int4*)dst)[q];
    atomicAdd(&g_cnt[d.x], 1);
    atomicAdd(&g_cnt[d.y], 1);
    atomicAdd(&g_cnt[d.z], 1);
    atomicAdd(&g_cnt[d.w], 1);
}

// block scan: 13 blocks x 1024 threads x 4 elems
__global__ void __launch_bounds__(1024) k_scan1() {
    int b = blockIdx.x, t = threadIdx.x;
    int base = b * 4096 + t * 4;
    int4 c = *(const int4*)&g_cnt[base];
    int s0 = c.x, s1 = s0 + c.y, s2 = s1 + c.z, s3 = s2 + c.w;
    int tot = s3;
    __shared__ int sh[1024];
    sh[t] = tot;
    __syncthreads();
    for (int o = 1; o < 1024; o <<= 1) {
        int v = (t >= o) ? sh[t - o] : 0;
        __syncthreads();
        sh[t] += v;
        __syncthreads();
    }
    int ex = sh[t] - tot;
    int4 outv = make_int4(ex, ex + s0, ex + s1, ex + s2);
    *(int4*)&g_part[base] = outv;
    if (t == 1023) g_bsum[b] = sh[1023];
}

__global__ void k_scan2(int nblocks) {
    if (threadIdx.x == 0) {
        int acc = 0;
        for (int i = 0; i < nblocks; i++) { g_boff[i] = acc; acc += g_bsum[i]; }
    }
}

__global__ void k_scan3() {
    int i = blockIdx.x * blockDim.x + threadIdx.x;
    if (i < N_PAD) {
        int r = g_part[i] + g_boff[i >> 12];
        g_rowptr[i] = r;
        g_cursor[i] = r;
    }
}

// 4 edges per thread: 4 independent atomic+store chains in flight
__global__ void k_permute(const int* __restrict__ src,
                          const int* __restrict__ dst) {
    int q = blockIdx.x * blockDim.x + threadIdx.x;
    if (q >= N_EDGES / 4) return;
    int4 s = ((const int4*)src)[q];
    int4 d = ((const int4*)dst)[q];
    int p0 = atomicAdd(&g_cursor[d.x], 1);
    int p1 = atomicAdd(&g_cursor[d.y], 1);
    int p2 = atomicAdd(&g_cursor[d.z], 1);
    int p3 = atomicAdd(&g_cursor[d.w], 1);
    g_srcsorted[p0] = s.x;
    g_srcsorted[p1] = s.y;
    g_srcsorted[p2] = s.z;
    g_srcsorted[p3] = s.w;
}

// ---------------------------------------------------------------------------
// CSR gather, high occupancy: thread = (node, float4 chunk), unroll 8.
// g_z[node] = h[node] + sum_{j->node} h[j]
__global__ void __launch_bounds__(256) k_gather(
        const float* __restrict__ xin, int use_x) {
    int gid = blockIdx.x * blockDim.x + threadIdx.x;
    int node = gid >> 4;
    int chunk = gid & 15;
    if (node >= N_NODES) return;
    const float4* __restrict__ hin4 =
        use_x ? (const float4*)xin : (const float4*)g_h;

    float4 a = hin4[(size_t)node * 16 + chunk];
    int beg = g_rowptr[node];
    int deg = g_cnt[node];
    int j = 0;
    for (; j + 8 <= deg; j += 8) {
        int s0 = g_srcsorted[beg + j + 0];
        int s1 = g_srcsorted[beg + j + 1];
        int s2 = g_srcsorted[beg + j + 2];
        int s3 = g_srcsorted[beg + j + 3];
        int s4 = g_srcsorted[beg + j + 4];
        int s5 = g_srcsorted[beg + j + 5];
        int s6 = g_srcsorted[beg + j + 6];
        int s7 = g_srcsorted[beg + j + 7];
        float4 v0 = hin4[(size_t)s0 * 16 + chunk];
        float4 v1 = hin4[(size_t)s1 * 16 + chunk];
        float4 v2 = hin4[(size_t)s2 * 16 + chunk];
        float4 v3 = hin4[(size_t)s3 * 16 + chunk];
        float4 v4 = hin4[(size_t)s4 * 16 + chunk];
        float4 v5 = hin4[(size_t)s5 * 16 + chunk];
        float4 v6 = hin4[(size_t)s6 * 16 + chunk];
        float4 v7 = hin4[(size_t)s7 * 16 + chunk];
        a.x += ((v0.x + v1.x) + (v2.x + v3.x)) + ((v4.x + v5.x) + (v6.x + v7.x));
        a.y += ((v0.y + v1.y) + (v2.y + v3.y)) + ((v4.y + v5.y) + (v6.y + v7.y));
        a.z += ((v0.z + v1.z) + (v2.z + v3.z)) + ((v4.z + v5.z) + (v6.z + v7.z));
        a.w += ((v0.w + v1.w) + (v2.w + v3.w)) + ((v4.w + v5.w) + (v6.w + v7.w));
    }
    for (; j + 2 <= deg; j += 2) {
        int s0 = g_srcsorted[beg + j + 0];
        int s1 = g_srcsorted[beg + j + 1];
        float4 v0 = hin4[(size_t)s0 * 16 + chunk];
        float4 v1 = hin4[(size_t)s1 * 16 + chunk];
        a.x += v0.x + v1.x; a.y += v0.y + v1.y;
        a.z += v0.z + v1.z; a.w += v0.w + v1.w;
    }
    if (j < deg) {
        int s0 = g_srcsorted[beg + j];
        float4 v0 = hin4[(size_t)s0 * 16 + chunk];
        a.x += v0.x; a.y += v0.y; a.z += v0.z; a.w += v0.w;
    }
    ((float4*)g_z)[(size_t)node * 16 + chunk] = a;
}

// ---------------------------------------------------------------------------
// Tiled MLP: z2 = relu( relu(z @ W1 + B1) @ W2 + B2 ) + fused BN stats.
// Block tile: 128 nodes x 64 features, 256 threads, thread tile 8x4.
__global__ void __launch_bounds__(256, 2) k_mlp(
        int layer,
        const float* __restrict__ W1, const float* __restrict__ B1,
        const float* __restrict__ W2, const float* __restrict__ B2) {
    extern __shared__ float smem[];
    float* sZT = smem;                        // [64][ZT_STRIDE] transposed z
    float* sW  = sZT + 64 * ZT_STRIDE;        // [64][64]
    float* sHT = sW + 64 * 64;                // [64][ZT_STRIDE] transposed hidden

    const int t  = threadIdx.x;
    const int tm = t & 15;
    const int tn = t >> 4;
    const int blockNode = blockIdx.x * 128;
    float* stats = g_stats + layer * 2 * DIM;

    for (int i = t; i < DIM * DIM; i += 256) sW[i] = W1[i];
    {
        int nLoc = t & 15;
        int f4   = t >> 4;
#pragma unroll
        for (int s = 0; s < 8; s++) {
            int m = s * 16 + nLoc;
            int node = blockNode + m;
            float4 v = make_float4(0.f, 0.f, 0.f, 0.f);
            if (node < N_NODES)
                v = ((const float4*)g_z)[(size_t)node * 16 + f4];
            sZT[(4 * f4 + 0) * ZT_STRIDE + m] = v.x;
            sZT[(4 * f4 + 1) * ZT_STRIDE + m] = v.y;
            sZT[(4 * f4 + 2) * ZT_STRIDE + m] = v.z;
            sZT[(4 * f4 + 3) * ZT_STRIDE + m] = v.w;
        }
    }
    __syncthreads();

    float acc[8][4];
    {
        float b0 = B1[4 * tn + 0], b1 = B1[4 * tn + 1];
        float b2 = B1[4 * tn + 2], b3 = B1[4 * tn + 3];
#pragma unroll
        for (int i = 0; i < 8; i++) {
            acc[i][0] = b0; acc[i][1] = b1; acc[i][2] = b2; acc[i][3] = b3;
        }
    }
#pragma unroll 4
    for (int k = 0; k < DIM; k++) {
        float4 a0 = *(const float4*)&sZT[k * ZT_STRIDE + 8 * tm];
        float4 a1 = *(const float4*)&sZT[k * ZT_STRIDE + 8 * tm + 4];
        float4 b  = *(const float4*)&sW[k * DIM + 4 * tn];
        float av[8] = {a0.x, a0.y, a0.z, a0.w, a1.x, a1.y, a1.z, a1.w};
#pragma unroll
        for (int i = 0; i < 8; i++) {
            acc[i][0] += av[i] * b.x;
            acc[i][1] += av[i] * b.y;
            acc[i][2] += av[i] * b.z;
            acc[i][3] += av[i] * b.w;
        }
    }
#pragma unroll
    for (int i = 0; i < 8; i++) {
        int m = 8 * tm + i;
#pragma unroll
        for (int j = 0; j < 4; j++)
            sHT[(4 * tn + j) * ZT_STRIDE + m] = fmaxf(acc[i][j], 0.f);
    }
    __syncthreads();
    for (int i = t; i < DIM * DIM; i += 256) sW[i] = W2[i];
    __syncthreads();

    {
        float b0 = B2[4 * tn + 0], b1 = B2[4 * tn + 1];
        float b2 = B2[4 * tn + 2], b3 = B2[4 * tn + 3];
#pragma unroll
        for (int i = 0; i < 8; i++) {
            acc[i][0] = b0; acc[i][1] = b1; acc[i][2] = b2; acc[i][3] = b3;
        }
    }
#pragma unroll 4
    for (int k = 0; k < DIM; k++) {
        float4 a0 = *(const float4*)&sHT[k * ZT_STRIDE + 8 * tm];
        float4 a1 = *(const float4*)&sHT[k * ZT_STRIDE + 8 * tm + 4];
        float4 b  = *(const float4*)&sW[k * DIM + 4 * tn];
        float av[8] = {a0.x, a0.y, a0.z, a0.w, a1.x, a1.y, a1.z, a1.w};
#pragma unroll
        for (int i = 0; i < 8; i++) {
            acc[i][0] += av[i] * b.x;
            acc[i][1] += av[i] * b.y;
            acc[i][2] += av[i] * b.z;
            acc[i][3] += av[i] * b.w;
        }
    }

    float psum[4] = {0.f, 0.f, 0.f, 0.f};
    float psq [4] = {0.f, 0.f, 0.f, 0.f};
#pragma unroll
    for (int i = 0; i < 8; i++) {
        int node = blockNode + 8 * tm + i;
        float v0 = fmaxf(acc[i][0], 0.f);
        float v1 = fmaxf(acc[i][1], 0.f);
        float v2 = fmaxf(acc[i][2], 0.f);
        float v3 = fmaxf(acc[i][3], 0.f);
        if (node < N_NODES) {
            *(float4*)(g_z2 + (size_t)node * DIM + 4 * tn) =
                make_float4(v0, v1, v2, v3);
            psum[0] += v0; psum[1] += v1; psum[2] += v2; psum[3] += v3;
            psq[0] += v0 * v0; psq[1] += v1 * v1;
            psq[2] += v2 * v2; psq[3] += v3 * v3;
        }
    }
#pragma unroll
    for (int ofs = 1; ofs <= 8; ofs <<= 1) {
#pragma unroll
        for (int j = 0; j < 4; j++) {
            psum[j] += __shfl_xor_sync(0xffffffffu, psum[j], ofs);
            psq [j] += __shfl_xor_sync(0xffffffffu, psq [j], ofs);
        }
    }
    if (tm == 0) {
#pragma unroll
        for (int j = 0; j < 4; j++) {
            atomicAdd(&stats[4 * tn + j], psum[j]);
            atomicAdd(&stats[DIM + 4 * tn + j], psq[j]);
        }
    }
}

// ---------------------------------------------------------------------------
// BN apply + next-layer input + pooled accumulation (run-length atomics).
__global__ void __launch_bounds__(256) k_bn(
        const float* __restrict__ gamma,
        const float* __restrict__ beta,
        const int* __restrict__ batch,
        int layer, int last) {
    int t = blockIdx.x * blockDim.x + threadIdx.x;
    int d = t & 63;
    int nodeBase = (t >> 6) * 8;
    if (nodeBase >= N_NODES) return;
    const float* stats = g_stats + layer * 2 * DIM;
    int layerOff = layer * DIM;

    const float invN = 1.f / N_NODES;
    float mean = stats[d] * invN;
    float var  = fmaxf(stats[DIM + d] * invN - mean * mean, 0.f);
    float scale = rsqrtf(var + 1e-5f) * gamma[d];
    float shift = beta[d] - mean * scale;

    int curG = batch[nodeBase];
    float poolAcc = 0.f;
#pragma unroll
    for (int i = 0; i < 8; i++) {
        int node = nodeBase + i;
        if (node >= N_NODES) break;
        size_t idx = (size_t)node * DIM + d;
        float v = g_z2[idx] * scale + shift;
        if (!last) g_h[idx] = v;
        int g = batch[node];
        if (g != curG) {
            atomicAdd(&g_pooled[curG * D3 + layerOff + d], poolAcc);
            poolAcc = 0.f;
            curG = g;
        }
        poolAcc += v;
    }
    atomicAdd(&g_pooled[curG * D3 + layerOff + d], poolAcc);
}

// out = relu(pooled @ PW1 + PB1) @ PW2 + PB2,  one graph per block
__global__ void __launch_bounds__(D3) k_final(
        const float* __restrict__ PW1, const float* __restrict__ PB1,
        const float* __restrict__ PW2, const float* __restrict__ PB2,
        float* __restrict__ out) {
    int g = blockIdx.x;
    int t = threadIdx.x;
    __shared__ float row[D3];
    __shared__ float hid[D3];
    row[t] = g_pooled[g * D3 + t];
    __syncthreads();
    float acc = PB1[t];
#pragma unroll 8
    for (int k = 0; k < D3; k++) acc += row[k] * PW1[k * D3 + t];
    hid[t] = fmaxf(acc, 0.f);
    __syncthreads();
    float a2 = PB2[t];
#pragma unroll 8
    for (int k = 0; k < D3; k++) a2 += hid[k] * PW2[k * D3 + t];
    out[g * D3 + t] = a2;
}

// ---------------------------------------------------------------------------
extern "C" void kernel_launch(void* const* d_in, const int* in_sizes, int n_in,
                              void* d_out, int out_size) {
    const float* x     = (const float*)d_in[0];
    const int*   ei    = (const int*)d_in[1];     // [2, N_EDGES] int32
    const int*   batch = (const int*)d_in[2];     // [N_NODES]    int32
    const float* W1 = (const float*)d_in[3];   // [3,64,64]
    const float* B1 = (const float*)d_in[4];
    const float* W2 = (const float*)d_in[5];
    const float* B2 = (const float*)d_in[6];
    const float* gamma = (const float*)d_in[7];
    const float* beta  = (const float*)d_in[8];
    const float* PW1 = (const float*)d_in[9];
    const float* PB1 = (const float*)d_in[10];
    const float* PW2 = (const float*)d_in[11];
    const float* PB2 = (const float*)d_in[12];
    float* out = (float*)d_out;

    const int* src = ei;
    const int* dst = ei + N_EDGES;

    const int mlpSmem = (64 * ZT_STRIDE + 64 * 64 + 64 * ZT_STRIDE) * 4;
    static int attrDone = 0;
    if (!attrDone) {
        cudaFuncSetAttribute(k_mlp, cudaFuncAttributeMaxDynamicSharedMemorySize,
                             mlpSmem);
        attrDone = 1;
    }

    const int zeroTot = N_PAD + N_LAYERS * 2 * DIM + N_GRAPHS * D3;
    k_zero_all<<<(zeroTot + 255) / 256, 256>>>();
    k_hist<<<(N_EDGES / 4 + 255) / 256, 256>>>(dst);
    k_scan1<<<N_PAD / 4096, 1024>>>();
    k_scan2<<<1, 32>>>(N_PAD / 4096);
    k_scan3<<<(N_PAD + 255) / 256, 256>>>();
    k_permute<<<(N_EDGES / 4 + 255) / 256, 256>>>(src, dst);

    const int gatherThreads = N_NODES * 16;
    const int bnThreads = 64 * ((N_NODES + 7) / 8);
    const int bnBlocks  = (bnThreads + 255) / 256;

    for (int l = 0; l < N_LAYERS; l++) {
        k_gather<<<(gatherThreads + 255) / 256, 256>>>(x, l == 0 ? 1 : 0);
        k_mlp<<<(N_NODES + 127) / 128, 256, mlpSmem>>>(
            l,
            W1 + l * DIM * DIM, B1 + l * DIM,
            W2 + l * DIM * DIM, B2 + l * DIM);
        k_bn<<<bnBlocks, 256>>>(gamma + l * DIM, beta + l * DIM,
                                batch, l, l == N_LAYERS - 1);
    }
    k_final<<<N_GRAPHS, D3>>>(PW1, PB1, PW2, PB2, out);
}

// round 16
// speedup vs baseline: 1.2030x; 1.1498x over previous
#include <cuda_runtime.h>
#include <cuda_bf16.h>
#include <cstdio>

#define N_NODES 50000
#define N_EDGES 800000
#define DIM 64
#define N_GRAPHS 256
#define N_LAYERS 3
#define D3 (DIM * N_LAYERS)   // 192
#define NV (N_NODES * DIM)    // 3,200,000

#define ZT_STRIDE 132         // padded row stride for transposed tiles
#define N_PAD 53248           // 13 * 4096, padded node count for scan

// packed fp32x2 helpers (Blackwell FFMA2 — PTX-only)
#define FMA2(d, a, b, c) \
    asm("fma.rn.f32x2 %0, %1, %2, %3;" : "=l"(d) : "l"(a), "l"(b), "l"(c))
#define PACK2(out, lo, hi) \
    asm("mov.b64 %0, {%1, %2};" : "=l"(out) : "f"(lo), "f"(hi))
#define UNPACK2(lo, hi, in) \
    asm("mov.b64 {%0, %1}, %2;" : "=f"(lo), "=f"(hi) : "l"(in))

// ---------------- scratch (device globals; no allocation allowed) ----------
__device__ __align__(16) float g_z [NV];      // aggregated input (h + sum nbrs)
__device__ __align__(16) float g_z2[NV];      // post-MLP, pre-BN
__device__ __align__(16) float g_h [NV];      // post-BN (next layer input)
__device__ float g_stats[N_LAYERS * 2 * DIM]; // per-layer [sum | sumsq]
__device__ float g_pooled[N_GRAPHS * D3];

__device__ __align__(16) int g_cnt   [N_PAD]; // per-dst degree (histogram)
__device__ __align__(16) int g_part  [N_PAD]; // scan partials
__device__ int g_bsum[16];
__device__ int g_boff[16];
__device__ int g_rowptr[N_PAD];
__device__ int g_cursor[N_PAD];
__device__ int g_srcsorted[N_EDGES];

// ---------------------------------------------------------------------------
__global__ void k_zero_all() {
    int i = blockIdx.x * blockDim.x + threadIdx.x;
    if (i < N_PAD) g_cnt[i] = 0;
    else if (i < N_PAD + N_LAYERS * 2 * DIM) g_stats[i - N_PAD] = 0.f;
    else if (i < N_PAD + N_LAYERS * 2 * DIM + N_GRAPHS * D3)
        g_pooled[i - N_PAD - N_LAYERS * 2 * DIM] = 0.f;
}

__global__ void k_hist(const int* __restrict__ dst) {
    int e = blockIdx.x * blockDim.x + threadIdx.x;
    if (e < N_EDGES) atomicAdd(&g_cnt[dst[e]], 1);
}

// block scan: 13 blocks x 1024 threads x 4 elems
__global__ void __launch_bounds__(1024) k_scan1() {
    int b = blockIdx.x, t = threadIdx.x;
    int base = b * 4096 + t * 4;
    int4 c = *(const int4*)&g_cnt[base];
    int s0 = c.x, s1 = s0 + c.y, s2 = s1 + c.z, s3 = s2 + c.w;
    int tot = s3;
    __shared__ int sh[1024];
    sh[t] = tot;
    __syncthreads();
    for (int o = 1; o < 1024; o <<= 1) {
        int v = (t >= o) ? sh[t - o] : 0;
        __syncthreads();
        sh[t] += v;
        __syncthreads();
    }
    int ex = sh[t] - tot;
    int4 outv = make_int4(ex, ex + s0, ex + s1, ex + s2);
    *(int4*)&g_part[base] = outv;
    if (t == 1023) g_bsum[b] = sh[1023];
}

__global__ void k_scan2(int nblocks) {
    if (threadIdx.x == 0) {
        int acc = 0;
        for (int i = 0; i < nblocks; i++) { g_boff[i] = acc; acc += g_bsum[i]; }
    }
}

__global__ void k_scan3() {
    int i = blockIdx.x * blockDim.x + threadIdx.x;
    if (i < N_PAD) {
        int r = g_part[i] + g_boff[i >> 12];
        g_rowptr[i] = r;
        g_cursor[i] = r;
    }
}

__global__ void k_permute(const int* __restrict__ src,
                          const int* __restrict__ dst) {
    int e = blockIdx.x * blockDim.x + threadIdx.x;
    if (e < N_EDGES) {
        int pos = atomicAdd(&g_cursor[dst[e]], 1);
        g_srcsorted[pos] = src[e];
    }
}

// ---------------------------------------------------------------------------
// CSR gather, high occupancy: thread = (node, float4 chunk).
// g_z[node] = h[node] + sum_{j->node} h[j]
__global__ void __launch_bounds__(256) k_gather(
        const float* __restrict__ xin, int use_x) {
    int gid = blockIdx.x * blockDim.x + threadIdx.x;
    int node = gid >> 4;
    int chunk = gid & 15;
    if (node >= N_NODES) return;
    const float4* __restrict__ hin4 =
        use_x ? (const float4*)xin : (const float4*)g_h;

    float4 a = hin4[(size_t)node * 16 + chunk];
    int beg = g_rowptr[node];
    int deg = g_cnt[node];
    int j = 0;
    for (; j + 4 <= deg; j += 4) {
        int s0 = g_srcsorted[beg + j + 0];
        int s1 = g_srcsorted[beg + j + 1];
        int s2 = g_srcsorted[beg + j + 2];
        int s3 = g_srcsorted[beg + j + 3];
        float4 v0 = hin4[(size_t)s0 * 16 + chunk];
        float4 v1 = hin4[(size_t)s1 * 16 + chunk];
        float4 v2 = hin4[(size_t)s2 * 16 + chunk];
        float4 v3 = hin4[(size_t)s3 * 16 + chunk];
        a.x += (v0.x + v1.x) + (v2.x + v3.x);
        a.y += (v0.y + v1.y) + (v2.y + v3.y);
        a.z += (v0.z + v1.z) + (v2.z + v3.z);
        a.w += (v0.w + v1.w) + (v2.w + v3.w);
    }
    for (; j < deg; j++) {
        int s0 = g_srcsorted[beg + j];
        float4 v0 = hin4[(size_t)s0 * 16 + chunk];
        a.x += v0.x; a.y += v0.y; a.z += v0.z; a.w += v0.w;
    }
    ((float4*)g_z)[(size_t)node * 16 + chunk] = a;
}

// ---------------------------------------------------------------------------
// Tiled MLP with packed f32x2 FMA: z2 = relu( relu(z@W1+B1) @ W2 + B2 ).
// Block tile: 128 nodes x 64 feats, 256 threads, thread tile 8 nodes x 4 feats.
// Accumulators packed over node pairs: acc2[i2][j] = (node 2*i2, node 2*i2+1).
__global__ void __launch_bounds__(256, 2) k_mlp(
        int layer,
        const float* __restrict__ W1, const float* __restrict__ B1,
        const float* __restrict__ W2, const float* __restrict__ B2) {
    extern __shared__ float smem[];
    float* sZT = smem;                        // [64][ZT_STRIDE] transposed z
    float* sW  = sZT + 64 * ZT_STRIDE;        // [64][64]
    float* sHT = sW + 64 * 64;                // [64][ZT_STRIDE] transposed hidden

    const int t  = threadIdx.x;
    const int tm = t & 15;
    const int tn = t >> 4;
    const int blockNode = blockIdx.x * 128;
    float* stats = g_stats + layer * 2 * DIM;

    for (int i = t; i < DIM * DIM; i += 256) sW[i] = W1[i];
    {
        int nLoc = t & 15;
        int f4   = t >> 4;
#pragma unroll
        for (int s = 0; s < 8; s++) {
            int m = s * 16 + nLoc;
            int node = blockNode + m;
            float4 v = make_float4(0.f, 0.f, 0.f, 0.f);
            if (node < N_NODES)
                v = ((const float4*)g_z)[(size_t)node * 16 + f4];
            sZT[(4 * f4 + 0) * ZT_STRIDE + m] = v.x;
            sZT[(4 * f4 + 1) * ZT_STRIDE + m] = v.y;
            sZT[(4 * f4 + 2) * ZT_STRIDE + m] = v.z;
            sZT[(4 * f4 + 3) * ZT_STRIDE + m] = v.w;
        }
    }
    __syncthreads();

    // ---- GEMM1 (f32x2): acc2[i2][j] over node pairs ----
    unsigned long long acc2[4][4];
#pragma unroll
    for (int j = 0; j < 4; j++) {
        float bj = B1[4 * tn + j];
        unsigned long long bp; PACK2(bp, bj, bj);
#pragma unroll
        for (int i2 = 0; i2 < 4; i2++) acc2[i2][j] = bp;
    }
#pragma unroll 4
    for (int k = 0; k < DIM; k++) {
        ulonglong2 a01 = *(const ulonglong2*)&sZT[k * ZT_STRIDE + 8 * tm];
        ulonglong2 a23 = *(const ulonglong2*)&sZT[k * ZT_STRIDE + 8 * tm + 4];
        float4 b = *(const float4*)&sW[k * DIM + 4 * tn];
        unsigned long long bd0, bd1, bd2, bd3;
        PACK2(bd0, b.x, b.x); PACK2(bd1, b.y, b.y);
        PACK2(bd2, b.z, b.z); PACK2(bd3, b.w, b.w);
        unsigned long long ap[4] = {a01.x, a01.y, a23.x, a23.y};
#pragma unroll
        for (int i2 = 0; i2 < 4; i2++) {
            FMA2(acc2[i2][0], ap[i2], bd0, acc2[i2][0]);
            FMA2(acc2[i2][1], ap[i2], bd1, acc2[i2][1]);
            FMA2(acc2[i2][2], ap[i2], bd2, acc2[i2][2]);
            FMA2(acc2[i2][3], ap[i2], bd3, acc2[i2][3]);
        }
    }
    // relu -> store hidden transposed (pairs are contiguous nodes)
#pragma unroll
    for (int i2 = 0; i2 < 4; i2++) {
#pragma unroll
        for (int j = 0; j < 4; j++) {
            float v0, v1;
            UNPACK2(v0, v1, acc2[i2][j]);
            float2 h = make_float2(fmaxf(v0, 0.f), fmaxf(v1, 0.f));
            *(float2*)&sHT[(4 * tn + j) * ZT_STRIDE + 8 * tm + 2 * i2] = h;
        }
    }
    __syncthreads();
    for (int i = t; i < DIM * DIM; i += 256) sW[i] = W2[i];
    __syncthreads();

    // ---- GEMM2 (f32x2) ----
#pragma unroll
    for (int j = 0; j < 4; j++) {
        float bj = B2[4 * tn + j];
        unsigned long long bp; PACK2(bp, bj, bj);
#pragma unroll
        for (int i2 = 0; i2 < 4; i2++) acc2[i2][j] = bp;
    }
#pragma unroll 4
    for (int k = 0; k < DIM; k++) {
        ulonglong2 a01 = *(const ulonglong2*)&sHT[k * ZT_STRIDE + 8 * tm];
        ulonglong2 a23 = *(const ulonglong2*)&sHT[k * ZT_STRIDE + 8 * tm + 4];
        float4 b = *(const float4*)&sW[k * DIM + 4 * tn];
        unsigned long long bd0, bd1, bd2, bd3;
        PACK2(bd0, b.x, b.x); PACK2(bd1, b.y, b.y);
        PACK2(bd2, b.z, b.z); PACK2(bd3, b.w, b.w);
        unsigned long long ap[4] = {a01.x, a01.y, a23.x, a23.y};
#pragma unroll
        for (int i2 = 0; i2 < 4; i2++) {
            FMA2(acc2[i2][0], ap[i2], bd0, acc2[i2][0]);
            FMA2(acc2[i2][1], ap[i2], bd1, acc2[i2][1]);
            FMA2(acc2[i2][2], ap[i2], bd2, acc2[i2][2]);
            FMA2(acc2[i2][3], ap[i2], bd3, acc2[i2][3]);
        }
    }

    // ---- epilogue: relu, write z2, fused BN stats ----
    float psum[4] = {0.f, 0.f, 0.f, 0.f};
    float psq [4] = {0.f, 0.f, 0.f, 0.f};
#pragma unroll
    for (int i2 = 0; i2 < 4; i2++) {
        float va[2][4];
#pragma unroll
        for (int j = 0; j < 4; j++) {
            float v0, v1;
            UNPACK2(v0, v1, acc2[i2][j]);
            va[0][j] = fmaxf(v0, 0.f);
            va[1][j] = fmaxf(v1, 0.f);
        }
#pragma unroll
        for (int h = 0; h < 2; h++) {
            int node = blockNode + 8 * tm + 2 * i2 + h;
            if (node < N_NODES) {
                *(float4*)(g_z2 + (size_t)node * DIM + 4 * tn) =
                    make_float4(va[h][0], va[h][1], va[h][2], va[h][3]);
#pragma unroll
                for (int j = 0; j < 4; j++) {
                    psum[j] += va[h][j];
                    psq[j]  += va[h][j] * va[h][j];
                }
            }
        }
    }
#pragma unroll
    for (int ofs = 1; ofs <= 8; ofs <<= 1) {
#pragma unroll
        for (int j = 0; j < 4; j++) {
            psum[j] += __shfl_xor_sync(0xffffffffu, psum[j], ofs);
            psq [j] += __shfl_xor_sync(0xffffffffu, psq [j], ofs);
        }
    }
    if (tm == 0) {
#pragma unroll
        for (int j = 0; j < 4; j++) {
            atomicAdd(&stats[4 * tn + j], psum[j]);
            atomicAdd(&stats[DIM + 4 * tn + j], psq[j]);
        }
    }
}

// ---------------------------------------------------------------------------
// BN apply + next-layer input + pooled accumulation (run-length atomics).
__global__ void __launch_bounds__(256) k_bn(
        const float* __restrict__ gamma,
        const float* __restrict__ beta,
        const int* __restrict__ batch,
        int layer, int last) {
    int t = blockIdx.x * blockDim.x + threadIdx.x;
    int d = t & 63;
    int nodeBase = (t >> 6) * 8;
    if (nodeBase >= N_NODES) return;
    const float* stats = g_stats + layer * 2 * DIM;
    int layerOff = layer * DIM;

    const float invN = 1.f / N_NODES;
    float mean = stats[d] * invN;
    float var  = fmaxf(stats[DIM + d] * invN - mean * mean, 0.f);
    float scale = rsqrtf(var + 1e-5f) * gamma[d];
    float shift = beta[d] - mean * scale;

    int curG = batch[nodeBase];
    float poolAcc = 0.f;
#pragma unroll
    for (int i = 0; i < 8; i++) {
        int node = nodeBase + i;
        if (node >= N_NODES) break;
        size_t idx = (size_t)node * DIM + d;
        float v = g_z2[idx] * scale + shift;
        if (!last) g_h[idx] = v;
        int g = batch[node];
        if (g != curG) {
            atomicAdd(&g_pooled[curG * D3 + layerOff + d], poolAcc);
            poolAcc = 0.f;
            curG = g;
        }
        poolAcc += v;
    }
    atomicAdd(&g_pooled[curG * D3 + layerOff + d], poolAcc);
}

// out = relu(pooled @ PW1 + PB1) @ PW2 + PB2,  one graph per block
__global__ void __launch_bounds__(D3) k_final(
        const float* __restrict__ PW1, const float* __restrict__ PB1,
        const float* __restrict__ PW2, const float* __restrict__ PB2,
        float* __restrict__ out) {
    int g = blockIdx.x;
    int t = threadIdx.x;
    __shared__ float row[D3];
    __shared__ float hid[D3];
    row[t] = g_pooled[g * D3 + t];
    __syncthreads();
    float acc = PB1[t];
#pragma unroll 8
    for (int k = 0; k < D3; k++) acc += row[k] * PW1[k * D3 + t];
    hid[t] = fmaxf(acc, 0.f);
    __syncthreads();
    float a2 = PB2[t];
#pragma unroll 8
    for (int k = 0; k < D3; k++) a2 += hid[k] * PW2[k * D3 + t];
    out[g * D3 + t] = a2;
}

// ---------------------------------------------------------------------------
extern "C" void kernel_launch(void* const* d_in, const int* in_sizes, int n_in,
                              void* d_out, int out_size) {
    const float* x     = (const float*)d_in[0];
    const int*   ei    = (const int*)d_in[1];     // [2, N_EDGES] int32
    const int*   batch = (const int*)d_in[2];     // [N_NODES]    int32
    const float* W1 = (const float*)d_in[3];   // [3,64,64]
    const float* B1 = (const float*)d_in[4];
    const float* W2 = (const float*)d_in[5];
    const float* B2 = (const float*)d_in[6];
    const float* gamma = (const float*)d_in[7];
    const float* beta  = (const float*)d_in[8];
    const float* PW1 = (const float*)d_in[9];
    const float* PB1 = (const float*)d_in[10];
    const float* PW2 = (const float*)d_in[11];
    const float* PB2 = (const float*)d_in[12];
    float* out = (float*)d_out;

    const int* src = ei;
    const int* dst = ei + N_EDGES;

    const int mlpSmem = (64 * ZT_STRIDE + 64 * 64 + 64 * ZT_STRIDE) * 4;
    static int attrDone = 0;
    if (!attrDone) {
        cudaFuncSetAttribute(k_mlp, cudaFuncAttributeMaxDynamicSharedMemorySize,
                             mlpSmem);
        attrDone = 1;
    }

    const int zeroTot = N_PAD + N_LAYERS * 2 * DIM + N_GRAPHS * D3;
    k_zero_all<<<(zeroTot + 255) / 256, 256>>>();
    k_hist<<<(N_EDGES + 255) / 256, 256>>>(dst);
    k_scan1<<<N_PAD / 4096, 1024>>>();
    k_scan2<<<1, 32>>>(N_PAD / 4096);
    k_scan3<<<(N_PAD + 255) / 256, 256>>>();
    k_permute<<<(N_EDGES + 255) / 256, 256>>>(src, dst);

    const int gatherThreads = N_NODES * 16;
    const int bnThreads = 64 * ((N_NODES + 7) / 8);
    const int bnBlocks  = (bnThreads + 255) / 256;

    for (int l = 0; l < N_LAYERS; l++) {
        k_gather<<<(gatherThreads + 255) / 256, 256>>>(x, l == 0 ? 1 : 0);
        k_mlp<<<(N_NODES + 127) / 128, 256, mlpSmem>>>(
            l,
            W1 + l * DIM * DIM, B1 + l * DIM,
            W2 + l * DIM * DIM, B2 + l * DIM);
        k_bn<<<bnBlocks, 256>>>(gamma + l * DIM, beta + l * DIM,
                                batch, l, l == N_LAYERS - 1);
    }
    k_final<<<N_GRAPHS, D3>>>(PW1, PB1, PW2, PB2, out);
}

// round 17
// speedup vs baseline: 1.2225x; 1.0162x over previous
#include <cuda_runtime.h>
#include <cuda_bf16.h>
#include <cstdio>

#define N_NODES 50000
#define N_EDGES 800000
#define DIM 64
#define N_GRAPHS 256
#define N_LAYERS 3
#define D3 (DIM * N_LAYERS)   // 192
#define NV (N_NODES * DIM)    // 3,200,000

#define ZT_STRIDE 132         // padded row stride for transposed tiles
#define N_PAD 53248           // 13 * 4096, padded node count for scan

// packed fp32x2 helpers (Blackwell FFMA2 — PTX-only)
#define FMA2(d, a, b, c) \
    asm("fma.rn.f32x2 %0, %1, %2, %3;" : "=l"(d) : "l"(a), "l"(b), "l"(c))
#define PACK2(out, lo, hi) \
    asm("mov.b64 %0, {%1, %2};" : "=l"(out) : "f"(lo), "f"(hi))
#define UNPACK2(lo, hi, in) \
    asm("mov.b64 {%0, %1}, %2;" : "=f"(lo), "=f"(hi) : "l"(in))

// ---------------- scratch (device globals; no allocation allowed) ----------
__device__ __align__(16) float g_z [NV];      // aggregated input (h + sum nbrs)
__device__ __align__(16) float g_z2[NV];      // post-MLP, pre-BN
__device__ __align__(16) float g_h [NV];      // post-BN (next layer input)
__device__ float g_stats[N_LAYERS * 2 * DIM]; // per-layer [sum | sumsq]
__device__ float g_pooled[N_GRAPHS * D3];

__device__ __align__(16) int g_cnt   [N_PAD]; // per-dst degree (histogram)
__device__ __align__(16) int g_part  [N_PAD]; // scan partials
__device__ int g_bsum[16];
__device__ int g_rowptr[N_PAD];
__device__ int g_cursor[N_PAD];
__device__ int g_srcsorted[N_EDGES];

// ---------------------------------------------------------------------------
__global__ void k_zero_all() {
    int i = blockIdx.x * blockDim.x + threadIdx.x;
    if (i < N_PAD) g_cnt[i] = 0;
    else if (i < N_PAD + N_LAYERS * 2 * DIM) g_stats[i - N_PAD] = 0.f;
    else if (i < N_PAD + N_LAYERS * 2 * DIM + N_GRAPHS * D3)
        g_pooled[i - N_PAD - N_LAYERS * 2 * DIM] = 0.f;
}

__global__ void k_hist(const int* __restrict__ dst) {
    int e = blockIdx.x * blockDim.x + threadIdx.x;
    if (e < N_EDGES) atomicAdd(&g_cnt[dst[e]], 1);
}

// block scan: 13 blocks x 1024 threads x 4 elems
__global__ void __launch_bounds__(1024) k_scan1() {
    int b = blockIdx.x, t = threadIdx.x;
    int base = b * 4096 + t * 4;
    int4 c = *(const int4*)&g_cnt[base];
    int s0 = c.x, s1 = s0 + c.y, s2 = s1 + c.z, s3 = s2 + c.w;
    int tot = s3;
    __shared__ int sh[1024];
    sh[t] = tot;
    __syncthreads();
    for (int o = 1; o < 1024; o <<= 1) {
        int v = (t >= o) ? sh[t - o] : 0;
        __syncthreads();
        sh[t] += v;
        __syncthreads();
    }
    int ex = sh[t] - tot;
    int4 outv = make_int4(ex, ex + s0, ex + s1, ex + s2);
    *(int4*)&g_part[base] = outv;
    if (t == 1023) g_bsum[b] = sh[1023];
}

// scan3 absorbs the old scan2: each thread re-derives its block offset by
// summing <=12 g_bsum entries (L2-broadcast loads) — no serial kernel.
__global__ void k_scan3() {
    int i = blockIdx.x * blockDim.x + threadIdx.x;
    if (i < N_PAD) {
        int blk = i >> 12;
        int off = 0;
        for (int b = 0; b < blk; b++) off += g_bsum[b];
        int r = g_part[i] + off;
        g_rowptr[i] = r;
        g_cursor[i] = r;
    }
}

__global__ void k_permute(const int* __restrict__ src,
                          const int* __restrict__ dst) {
    int e = blockIdx.x * blockDim.x + threadIdx.x;
    if (e < N_EDGES) {
        int pos = atomicAdd(&g_cursor[dst[e]], 1);
        g_srcsorted[pos] = src[e];
    }
}

// ---------------------------------------------------------------------------
// CSR gather, high occupancy: thread = (node, float4 chunk).
// g_z[node] = h[node] + sum_{j->node} h[j]
__global__ void __launch_bounds__(256) k_gather(
        const float* __restrict__ xin, int use_x) {
    int gid = blockIdx.x * blockDim.x + threadIdx.x;
    int node = gid >> 4;
    int chunk = gid & 15;
    if (node >= N_NODES) return;
    const float4* __restrict__ hin4 =
        use_x ? (const float4*)xin : (const float4*)g_h;

    float4 a = hin4[(size_t)node * 16 + chunk];
    int beg = g_rowptr[node];
    int deg = g_cnt[node];
    int j = 0;
    for (; j + 4 <= deg; j += 4) {
        int s0 = g_srcsorted[beg + j + 0];
        int s1 = g_srcsorted[beg + j + 1];
        int s2 = g_srcsorted[beg + j + 2];
        int s3 = g_srcsorted[beg + j + 3];
        float4 v0 = hin4[(size_t)s0 * 16 + chunk];
        float4 v1 = hin4[(size_t)s1 * 16 + chunk];
        float4 v2 = hin4[(size_t)s2 * 16 + chunk];
        float4 v3 = hin4[(size_t)s3 * 16 + chunk];
        a.x += (v0.x + v1.x) + (v2.x + v3.x);
        a.y += (v0.y + v1.y) + (v2.y + v3.y);
        a.z += (v0.z + v1.z) + (v2.z + v3.z);
        a.w += (v0.w + v1.w) + (v2.w + v3.w);
    }
    for (; j < deg; j++) {
        int s0 = g_srcsorted[beg + j];
        float4 v0 = hin4[(size_t)s0 * 16 + chunk];
        a.x += v0.x; a.y += v0.y; a.z += v0.z; a.w += v0.w;
    }
    ((float4*)g_z)[(size_t)node * 16 + chunk] = a;
}

// ---------------------------------------------------------------------------
// Tiled MLP, packed f32x2 FMA, W pre-duplicated as (w,w) pairs in smem.
// Block tile: 128 nodes x 64 feats, 256 threads, thread tile 8 nodes x 4 feats.
__global__ void __launch_bounds__(256, 2) k_mlp(
        int layer,
        const float* __restrict__ W1, const float* __restrict__ B1,
        const float* __restrict__ W2, const float* __restrict__ B2) {
    extern __shared__ float smem[];
    float* sZT = smem;                        // [64][ZT_STRIDE] transposed z
    unsigned long long* sWd =
        (unsigned long long*)(smem + 64 * ZT_STRIDE);  // [64][64] dup pairs
    float* sHT = (float*)(sWd + 64 * 64);     // [64][ZT_STRIDE] hidden

    const int t  = threadIdx.x;
    const int tm = t & 15;
    const int tn = t >> 4;
    const int blockNode = blockIdx.x * 128;
    float* stats = g_stats + layer * 2 * DIM;

    for (int i = t; i < DIM * DIM; i += 256) {
        float w = W1[i];
        unsigned long long p; PACK2(p, w, w);
        sWd[i] = p;
    }
    {
        int nLoc = t & 15;
        int f4   = t >> 4;
#pragma unroll
        for (int s = 0; s < 8; s++) {
            int m = s * 16 + nLoc;
            int node = blockNode + m;
            float4 v = make_float4(0.f, 0.f, 0.f, 0.f);
            if (node < N_NODES)
                v = ((const float4*)g_z)[(size_t)node * 16 + f4];
            sZT[(4 * f4 + 0) * ZT_STRIDE + m] = v.x;
            sZT[(4 * f4 + 1) * ZT_STRIDE + m] = v.y;
            sZT[(4 * f4 + 2) * ZT_STRIDE + m] = v.z;
            sZT[(4 * f4 + 3) * ZT_STRIDE + m] = v.w;
        }
    }
    __syncthreads();

    // ---- GEMM1 (f32x2): acc2[i2][j] over node pairs ----
    unsigned long long acc2[4][4];
#pragma unroll
    for (int j = 0; j < 4; j++) {
        float bj = B1[4 * tn + j];
        unsigned long long bp; PACK2(bp, bj, bj);
#pragma unroll
        for (int i2 = 0; i2 < 4; i2++) acc2[i2][j] = bp;
    }
#pragma unroll 4
    for (int k = 0; k < DIM; k++) {
        ulonglong2 a01 = *(const ulonglong2*)&sZT[k * ZT_STRIDE + 8 * tm];
        ulonglong2 a23 = *(const ulonglong2*)&sZT[k * ZT_STRIDE + 8 * tm + 4];
        ulonglong2 b01 = *(const ulonglong2*)&sWd[k * DIM + 4 * tn];
        ulonglong2 b23 = *(const ulonglong2*)&sWd[k * DIM + 4 * tn + 2];
        unsigned long long ap[4] = {a01.x, a01.y, a23.x, a23.y};
#pragma unroll
        for (int i2 = 0; i2 < 4; i2++) {
            FMA2(acc2[i2][0], ap[i2], b01.x, acc2[i2][0]);
            FMA2(acc2[i2][1], ap[i2], b01.y, acc2[i2][1]);
            FMA2(acc2[i2][2], ap[i2], b23.x, acc2[i2][2]);
            FMA2(acc2[i2][3], ap[i2], b23.y, acc2[i2][3]);
        }
    }
    // relu -> store hidden transposed (pairs are contiguous nodes)
#pragma unroll
    for (int i2 = 0; i2 < 4; i2++) {
#pragma unroll
        for (int j = 0; j < 4; j++) {
            float v0, v1;
            UNPACK2(v0, v1, acc2[i2][j]);
            float2 h = make_float2(fmaxf(v0, 0.f), fmaxf(v1, 0.f));
            *(float2*)&sHT[(4 * tn + j) * ZT_STRIDE + 8 * tm + 2 * i2] = h;
        }
    }
    __syncthreads();
    for (int i = t; i < DIM * DIM; i += 256) {
        float w = W2[i];
        unsigned long long p; PACK2(p, w, w);
        sWd[i] = p;
    }
    __syncthreads();

    // ---- GEMM2 (f32x2) ----
#pragma unroll
    for (int j = 0; j < 4; j++) {
        float bj = B2[4 * tn + j];
        unsigned long long bp; PACK2(bp, bj, bj);
#pragma unroll
        for (int i2 = 0; i2 < 4; i2++) acc2[i2][j] = bp;
    }
#pragma unroll 4
    for (int k = 0; k < DIM; k++) {
        ulonglong2 a01 = *(const ulonglong2*)&sHT[k * ZT_STRIDE + 8 * tm];
        ulonglong2 a23 = *(const ulonglong2*)&sHT[k * ZT_STRIDE + 8 * tm + 4];
        ulonglong2 b01 = *(const ulonglong2*)&sWd[k * DIM + 4 * tn];
        ulonglong2 b23 = *(const ulonglong2*)&sWd[k * DIM + 4 * tn + 2];
        unsigned long long ap[4] = {a01.x, a01.y, a23.x, a23.y};
#pragma unroll
        for (int i2 = 0; i2 < 4; i2++) {
            FMA2(acc2[i2][0], ap[i2], b01.x, acc2[i2][0]);
            FMA2(acc2[i2][1], ap[i2], b01.y, acc2[i2][1]);
            FMA2(acc2[i2][2], ap[i2], b23.x, acc2[i2][2]);
            FMA2(acc2[i2][3], ap[i2], b23.y, acc2[i2][3]);
        }
    }

    // ---- epilogue: relu, write z2, fused BN stats ----
    float psum[4] = {0.f, 0.f, 0.f, 0.f};
    float psq [4] = {0.f, 0.f, 0.f, 0.f};
#pragma unroll
    for (int i2 = 0; i2 < 4; i2++) {
        float va[2][4];
#pragma unroll
        for (int j = 0; j < 4; j++) {
            float v0, v1;
            UNPACK2(v0, v1, acc2[i2][j]);
            va[0][j] = fmaxf(v0, 0.f);
            va[1][j] = fmaxf(v1, 0.f);
        }
#pragma unroll
        for (int h = 0; h < 2; h++) {
            int node = blockNode + 8 * tm + 2 * i2 + h;
            if (node < N_NODES) {
                *(float4*)(g_z2 + (size_t)node * DIM + 4 * tn) =
                    make_float4(va[h][0], va[h][1], va[h][2], va[h][3]);
#pragma unroll
                for (int j = 0; j < 4; j++) {
                    psum[j] += va[h][j];
                    psq[j]  += va[h][j] * va[h][j];
                }
            }
        }
    }
#pragma unroll
    for (int ofs = 1; ofs <= 8; ofs <<= 1) {
#pragma unroll
        for (int j = 0; j < 4; j++) {
            psum[j] += __shfl_xor_sync(0xffffffffu, psum[j], ofs);
            psq [j] += __shfl_xor_sync(0xffffffffu, psq [j], ofs);
        }
    }
    if (tm == 0) {
#pragma unroll
        for (int j = 0; j < 4; j++) {
            atomicAdd(&stats[4 * tn + j], psum[j]);
            atomicAdd(&stats[DIM + 4 * tn + j], psq[j]);
        }
    }
}

// ---------------------------------------------------------------------------
// BN apply + next-layer input + pooled accumulation (run-length atomics).
__global__ void __launch_bounds__(256) k_bn(
        const float* __restrict__ gamma,
        const float* __restrict__ beta,
        const int* __restrict__ batch,
        int layer, int last) {
    int t = blockIdx.x * blockDim.x + threadIdx.x;
    int d = t & 63;
    int nodeBase = (t >> 6) * 8;
    if (nodeBase >= N_NODES) return;
    const float* stats = g_stats + layer * 2 * DIM;
    int layerOff = layer * DIM;

    const float invN = 1.f / N_NODES;
    float mean = stats[d] * invN;
    float var  = fmaxf(stats[DIM + d] * invN - mean * mean, 0.f);
    float scale = rsqrtf(var + 1e-5f) * gamma[d];
    float shift = beta[d] - mean * scale;

    int curG = batch[nodeBase];
    float poolAcc = 0.f;
#pragma unroll
    for (int i = 0; i < 8; i++) {
        int node = nodeBase + i;
        if (node >= N_NODES) break;
        size_t idx = (size_t)node * DIM + d;
        float v = g_z2[idx] * scale + shift;
        if (!last) g_h[idx] = v;
        int g = batch[node];
        if (g != curG) {
            atomicAdd(&g_pooled[curG * D3 + layerOff + d], poolAcc);
            poolAcc = 0.f;
            curG = g;
        }
        poolAcc += v;
    }
    atomicAdd(&g_pooled[curG * D3 + layerOff + d], poolAcc);
}

// out = relu(pooled @ PW1 + PB1) @ PW2 + PB2,  one graph per block
__global__ void __launch_bounds__(D3) k_final(
        const float* __restrict__ PW1, const float* __restrict__ PB1,
        const float* __restrict__ PW2, const float* __restrict__ PB2,
        float* __restrict__ out) {
    int g = blockIdx.x;
    int t = threadIdx.x;
    __shared__ float row[D3];
    __shared__ float hid[D3];
    row[t] = g_pooled[g * D3 + t];
    __syncthreads();
    float acc = PB1[t];
#pragma unroll 8
    for (int k = 0; k < D3; k++) acc += row[k] * PW1[k * D3 + t];
    hid[t] = fmaxf(acc, 0.f);
    __syncthreads();
    float a2 = PB2[t];
#pragma unroll 8
    for (int k = 0; k < D3; k++) a2 += hid[k] * PW2[k * D3 + t];
    out[g * D3 + t] = a2;
}

// ---------------------------------------------------------------------------
extern "C" void kernel_launch(void* const* d_in, const int* in_sizes, int n_in,
                              void* d_out, int out_size) {
    const float* x     = (const float*)d_in[0];
    const int*   ei    = (const int*)d_in[1];     // [2, N_EDGES] int32
    const int*   batch = (const int*)d_in[2];     // [N_NODES]    int32
    const float* W1 = (const float*)d_in[3];   // [3,64,64]
    const float* B1 = (const float*)d_in[4];
    const float* W2 = (const float*)d_in[5];
    const float* B2 = (const float*)d_in[6];
    const float* gamma = (const float*)d_in[7];
    const float* beta  = (const float*)d_in[8];
    const float* PW1 = (const float*)d_in[9];
    const float* PB1 = (const float*)d_in[10];
    const float* PW2 = (const float*)d_in[11];
    const float* PB2 = (const float*)d_in[12];
    float* out = (float*)d_out;

    const int* src = ei;
    const int* dst = ei + N_EDGES;

    const int mlpSmem = 64 * ZT_STRIDE * 4 + 64 * 64 * 8 + 64 * ZT_STRIDE * 4;
    static int attrDone = 0;
    if (!attrDone) {
        cudaFuncSetAttribute(k_mlp, cudaFuncAttributeMaxDynamicSharedMemorySize,
                             mlpSmem);
        attrDone = 1;
    }

    const int zeroTot = N_PAD + N_LAYERS * 2 * DIM + N_GRAPHS * D3;
    k_zero_all<<<(zeroTot + 255) / 256, 256>>>();
    k_hist<<<(N_EDGES + 255) / 256, 256>>>(dst);
    k_scan1<<<N_PAD / 4096, 1024>>>();
    k_scan3<<<(N_PAD + 255) / 256, 256>>>();
    k_permute<<<(N_EDGES + 255) / 256, 256>>>(src, dst);

    const int gatherThreads = N_NODES * 16;
    const int bnThreads = 64 * ((N_NODES + 7) / 8);
    const int bnBlocks  = (bnThreads + 255) / 256;

    for (int l = 0; l < N_LAYERS; l++) {
        k_gather<<<(gatherThreads + 255) / 256, 256>>>(x, l == 0 ? 1 : 0);
        k_mlp<<<(N_NODES + 127) / 128, 256, mlpSmem>>>(
            l,
            W1 + l * DIM * DIM, B1 + l * DIM,
            W2 + l * DIM * DIM, B2 + l * DIM);
        k_bn<<<bnBlocks, 256>>>(gamma + l * DIM, beta + l * DIM,
                                batch, l, l == N_LAYERS - 1);
    }
    k_final<<<N_GRAPHS, D3>>>(PW1, PB1, PW2, PB2, out);
}